// round 7
// baseline (speedup 1.0000x reference)
#include <cuda_runtime.h>
#include <cstdint>

#define N_NODES 10000
#define N_EDGES_MAX 320000
#define BB 4
#define TT 12
#define FINF 2
#define HID 64
#define OUTD 16
#define NB (N_NODES*BB)        /* 40000 rows (n,b) */
#define NC (BB*FINF*TT)        /* 96 features per node */

#define TILE_R 272             /* rows per block: 148 blocks = 1 wave */
#define NTHREADS 544           /* 2 threads per row (halves of 64 cols) */
#define GRID_STEPS 148
#define NODES_PER_BLK 68       /* 272/4 */

// ---------------- device scratch ----------------
__device__ float g_deg[N_NODES];
__device__ float g_dinv[N_NODES];
__device__ int   g_count[N_NODES];
__device__ int   g_rowptr[N_NODES + 1];
__device__ int   g_cursor[N_NODES];
__device__ int   g_csrc[N_EDGES_MAX];
__device__ float g_cw[N_EDGES_MAX];
__device__ float g_xT[N_NODES * NC];
__device__ float g_ax[N_NODES * NC];
__device__ float g_M[384];    // folded x-path: [gate(3)][fin(2)][64]
__device__ float g_gb[192];   // folded gate bias

// ---------------- packed f32x2 helpers ----------------
typedef unsigned long long u64t;
__device__ __forceinline__ u64t pk2(float lo, float hi) {
    u64t r; asm("mov.b64 %0, {%1, %2};" : "=l"(r) : "f"(lo), "f"(hi)); return r;
}
__device__ __forceinline__ u64t dup2(float x) {
    u64t r; asm("mov.b64 %0, {%1, %1};" : "=l"(r) : "f"(x)); return r;
}
__device__ __forceinline__ void up2(float& lo, float& hi, u64t v) {
    asm("mov.b64 {%0, %1}, %2;" : "=f"(lo), "=f"(hi) : "l"(v));
}
__device__ __forceinline__ void fma2(u64t& d, u64t a, u64t b) {
    asm("fma.rn.f32x2 %0, %1, %2, %0;" : "+l"(d) : "l"(a), "l"(b));
}
// partner (lane^1) sum of a packed pair
__device__ __forceinline__ u64t pair_sum(u64t v) {
    float lo, hi; up2(lo, hi, v);
    float plo = __shfl_xor_sync(0xffffffffu, lo, 1);
    float phi = __shfl_xor_sync(0xffffffffu, hi, 1);
    return pk2(lo + plo, hi + phi);
}
__device__ __forceinline__ u64t sel64(int o, u64t a_if1, u64t b_if0) {
    return o ? a_if1 : b_if0;
}

__device__ __forceinline__ float fast_sigmoid(float v) {
    return __fdividef(1.f, 1.f + __expf(-v));
}
__device__ __forceinline__ float fast_tanh(float v) {
    float e = __expf(-2.f * fabsf(v));
    float th = __fdividef(1.f - e, 1.f + e);
    return copysignf(th, v);
}

// ---------------- launch 1: transpose x + init deg/count ----------------
__global__ void k_xT_zero(const float* __restrict__ x) {
    int i = blockIdx.x * blockDim.x + threadIdx.x;
    if (i < N_NODES) { g_deg[i] = 1.0f; g_count[i] = 0; }
    if (i >= N_NODES * NC) return;
    int n = i / NC, c = i % NC;
    int b = c / (FINF * TT);
    int rem = c % (FINF * TT);
    int f = rem / TT, t = rem % TT;
    g_xT[i] = x[(((size_t)b * N_NODES + n) * FINF + f) * TT + t];
}

// ---------------- launch 2: per-edge degree + count ----------------
__global__ void k_edge(const int* __restrict__ ei, const float* __restrict__ ew, int E) {
    int e = blockIdx.x * blockDim.x + threadIdx.x;
    if (e >= E) return;
    int d = ei[E + e];
    atomicAdd(&g_deg[d], ew[e]);
    atomicAdd(&g_count[d], 1);
}

// ---------------- launch 3: scan counts -> rowptr/cursor, and dinv ----------------
__global__ void k_scan_dinv() {
    __shared__ int sums[1024];
    const int CH = 10;
    int tid = threadIdx.x;
    int base = tid * CH;
    int local[CH];
    int s = 0;
    for (int j = 0; j < CH; j++) {
        int idx = base + j;
        int v = (idx < N_NODES) ? g_count[idx] : 0;
        local[j] = s;
        s += v;
    }
    sums[tid] = s;
    __syncthreads();
    for (int off = 1; off < 1024; off <<= 1) {
        int v = (tid >= off) ? sums[tid - off] : 0;
        __syncthreads();
        sums[tid] += v;
        __syncthreads();
    }
    int offset = (tid > 0) ? sums[tid - 1] : 0;
    for (int j = 0; j < CH; j++) {
        int idx = base + j;
        if (idx <= N_NODES) {
            int v = offset + local[j];
            g_rowptr[idx] = v;
            if (idx < N_NODES) g_cursor[idx] = v;
        }
    }
    for (int n = tid; n < N_NODES; n += 1024)
        g_dinv[n] = rsqrtf(g_deg[n]);
}

// ---------------- launch 4: scatter edges into CSR with normalized weight ----------------
__global__ void k_scatter(const int* __restrict__ ei, const float* __restrict__ ew, int E) {
    int e = blockIdx.x * blockDim.x + threadIdx.x;
    if (e >= E) return;
    int s = ei[e];
    int d = ei[E + e];
    int pos = atomicAdd(&g_cursor[d], 1);
    g_csrc[pos] = s;
    g_cw[pos] = g_dinv[s] * ew[e] * g_dinv[d];
}

// ---------------- launch 5: aggregate + fold (fold in last block) ----------------
__global__ void k_agg_fold(const float* __restrict__ Wz, const float* __restrict__ bz,
                           const float* __restrict__ Wr, const float* __restrict__ br,
                           const float* __restrict__ Wh, const float* __restrict__ bh,
                           const float* __restrict__ Lz, const float* __restrict__ Lzb,
                           const float* __restrict__ Lr, const float* __restrict__ Lrb,
                           const float* __restrict__ Lh, const float* __restrict__ Lhb) {
    if (blockIdx.x == gridDim.x - 1) {
        int tid = threadIdx.x;
        if (tid >= 192) return;
        int g = tid >> 6, j = tid & 63;
        const float* W  = (g == 0) ? Wz  : (g == 1) ? Wr  : Wh;
        const float* bv = (g == 0) ? bz  : (g == 1) ? br  : bh;
        const float* L  = (g == 0) ? Lz  : (g == 1) ? Lr  : Lh;
        const float* Lb = (g == 0) ? Lzb : (g == 1) ? Lrb : Lhb;
        float m0 = 0.f, m1 = 0.f, gbv = 0.f;
        for (int m = 0; m < 64; m++) {
            float l = L[m * 64 + j];
            m0 += W[m] * l;
            m1 += W[64 + m] * l;
            gbv += bv[m] * l;
        }
        g_M[g * 128 + j] = m0;
        g_M[g * 128 + 64 + j] = m1;
        g_gb[g * 64 + j] = gbv + Lb[j];
        return;
    }
    int warp = (blockIdx.x * blockDim.x + threadIdx.x) >> 5;
    int lane = threadIdx.x & 31;
    if (warp >= N_NODES) return;
    int n = warp;
    float dv = g_dinv[n];
    float self_w = dv * dv;
    float a0 = self_w * g_xT[(size_t)n * NC + lane];
    float a1 = self_w * g_xT[(size_t)n * NC + lane + 32];
    float a2 = self_w * g_xT[(size_t)n * NC + lane + 64];
    int e0 = g_rowptr[n], e1 = g_rowptr[n + 1];
    for (int e = e0; e < e1; e++) {
        int s = g_csrc[e];
        float w = g_cw[e];
        const float* xs = &g_xT[(size_t)s * NC];
        a0 += w * xs[lane];
        a1 += w * xs[lane + 32];
        a2 += w * xs[lane + 64];
    }
    g_ax[(size_t)n * NC + lane] = a0;
    g_ax[(size_t)n * NC + lane + 32] = a1;
    g_ax[(size_t)n * NC + lane + 64] = a2;
}

// ---------------- launch 6: persistent GRU, H register-resident, NO barriers in t-loop ----
// smem (floats): sW1[64][128] (Lz_bot|Lr_bot), sW2[64][64], sLin[64][16],
//                sM[384], sGb[192], sLb[16], sAx[68][96]
#define SMEM_FLOATS (64*128 + 64*64 + 64*16 + 384 + 192 + 16 + NODES_PER_BLK*96)

__global__ __launch_bounds__(NTHREADS, 1)
void k_steps(const float* __restrict__ Lz, const float* __restrict__ Lr,
             const float* __restrict__ Lh, const float* __restrict__ lw,
             const float* __restrict__ lb, float* __restrict__ out) {
    extern __shared__ float sm[];
    float* sW1  = sm;                 // [k][0..63]=Lz_bot, [k][64..127]=Lr_bot
    float* sW2  = sW1 + 64 * 128;     // Lh_bot
    float* sLin = sW2 + 64 * 64;
    float* sM   = sLin + 64 * 16;
    float* sGb  = sM + 384;
    float* sLb  = sGb + 192;
    float* sAx  = sLb + 16;           // [68][96]

    int tid = threadIdx.x;
    int n0 = blockIdx.x * NODES_PER_BLK;

    // ---- one-time loads ----
    for (int i = tid; i < 64 * 128; i += NTHREADS) {
        int k = i >> 7, j = i & 127;
        sW1[i] = (j < 64) ? Lz[(64 + k) * 64 + j] : Lr[(64 + k) * 64 + (j - 64)];
    }
    for (int i = tid; i < 64 * 64; i += NTHREADS)
        sW2[i] = Lh[(64 + (i >> 6)) * 64 + (i & 63)];
    for (int i = tid; i < 64 * 16; i += NTHREADS) sLin[i] = lw[i];
    for (int i = tid; i < 384; i += NTHREADS) sM[i] = g_M[i];
    for (int i = tid; i < 192; i += NTHREADS) sGb[i] = g_gb[i];
    if (tid < 16) sLb[tid] = lb[tid];
    for (int i = tid; i < NODES_PER_BLK * 96; i += NTHREADS) {
        int nn = i / 96, c = i % 96;
        int n = n0 + nn;
        sAx[i] = (n < N_NODES) ? g_ax[(size_t)n * NC + c] : 0.f;
    }
    __syncthreads();   // the ONLY block-wide barrier

    int r = tid >> 1;            // row within block: 0..271
    int o = tid & 1;             // column half: cols [o*32, o*32+32)
    int o32 = o * 32;
    int row = blockIdx.x * TILE_R + r;
    int nn = r >> 2, bbl = r & 3;
    bool valid = row < NB;
    int n_g = row >> 2, b_g = row & 3;

    const float* sW1o  = sW1 + o32 * 128;   // rows k = o32..o32+31
    const float* sW2o  = sW2 + o32 * 64;
    const float* sLino = sLin + o32 * 16;
    const float* axp0  = sAx + nn * 96 + (bbl * 2) * TT;
    const float* axp1  = axp0 + TT;

    const u64t* gbZ = (const u64t*)sGb;
    const u64t* gbR = (const u64t*)(sGb + 64);
    const u64t* gbH = (const u64t*)(sGb + 128);
    const u64t* M00 = (const u64t*)sM;
    const u64t* M01 = (const u64t*)(sM + 64);
    const u64t* M10 = (const u64t*)(sM + 128);
    const u64t* M11 = (const u64t*)(sM + 192);
    const u64t* M20 = (const u64t*)(sM + 256);
    const u64t* M21 = (const u64t*)(sM + 320);
    const u64t* Lbp = (const u64t*)sLb;

    float hl[32];                 // H[row, o32 + i], register-resident
#pragma unroll
    for (int i = 0; i < 32; i++) hl[i] = 0.f;

    for (int t = 0; t < TT; t++) {
        float ax0 = axp0[t], ax1 = axp1[t];
        u64t a0d = dup2(ax0), a1d = dup2(ax1);

        // ---- fused Z+R partial GEMM over own k-half, all 64 output cols ----
        u64t accZ[32], accR[32];
#pragma unroll
        for (int q = 0; q < 32; q++) {
            u64t z = gbZ[q]; fma2(z, a0d, M00[q]); fma2(z, a1d, M01[q]); accZ[q] = z;
            u64t rr = gbR[q]; fma2(rr, a0d, M10[q]); fma2(rr, a1d, M11[q]); accR[q] = rr;
        }
        // halve the x-path init (it will be pair-summed; full value = sum of halves/... )
        // NOTE: init added in BOTH threads then pair-summed would double it; scale by 0.5:
#pragma unroll
        for (int q = 0; q < 32; q++) {
            float zl, zh, rl, rh;
            up2(zl, zh, accZ[q]); accZ[q] = pk2(0.5f * zl, 0.5f * zh);
            up2(rl, rh, accR[q]); accR[q] = pk2(0.5f * rl, 0.5f * rh);
        }
#pragma unroll
        for (int i = 0; i < 32; i++) {
            u64t a = dup2(hl[i]);
            const u64t* wz = (const u64t*)(sW1o + i * 128);
            const u64t* wr = wz + 32;
#pragma unroll
            for (int q = 0; q < 32; q++) { fma2(accZ[q], a, wz[q]); fma2(accR[q], a, wr[q]); }
        }
#pragma unroll
        for (int q = 0; q < 32; q++) { accZ[q] = pair_sum(accZ[q]); accR[q] = pair_sum(accR[q]); }

        // own halves -> sigmoid; hr = H .* sigmoid(R)
        u64t zOwn[16];
        float hr[32];
#pragma unroll
        for (int q = 0; q < 16; q++) {
            u64t zq = sel64(o, accZ[q + 16], accZ[q]);
            u64t rq = sel64(o, accR[q + 16], accR[q]);
            float zl, zh, rl, rh;
            up2(zl, zh, zq); up2(rl, rh, rq);
            zOwn[q] = pk2(fast_sigmoid(zl), fast_sigmoid(zh));
            hr[2 * q]     = hl[2 * q]     * fast_sigmoid(rl);
            hr[2 * q + 1] = hl[2 * q + 1] * fast_sigmoid(rh);
        }

        // ---- candidate partial GEMM ----
        u64t accH[32];
#pragma unroll
        for (int q = 0; q < 32; q++) {
            u64t h = gbH[q]; fma2(h, a0d, M20[q]); fma2(h, a1d, M21[q]);
            float l, hgh; up2(l, hgh, h);
            accH[q] = pk2(0.5f * l, 0.5f * hgh);
        }
#pragma unroll
        for (int i = 0; i < 32; i++) {
            u64t a = dup2(hr[i]);
            const u64t* w2 = (const u64t*)(sW2o + i * 64);
#pragma unroll
            for (int q = 0; q < 32; q++) fma2(accH[q], a, w2[q]);
        }
#pragma unroll
        for (int q = 0; q < 32; q++) accH[q] = pair_sum(accH[q]);

        // ---- update H (own cols) ----
#pragma unroll
        for (int q = 0; q < 16; q++) {
            u64t hq = sel64(o, accH[q + 16], accH[q]);
            float c0, c1; up2(c0, c1, hq);
            float t0 = fast_tanh(c0), t1 = fast_tanh(c1);
            float z0, z1; up2(z0, z1, zOwn[q]);
            hl[2 * q]     = t0 + z0 * (hl[2 * q]     - t0);
            hl[2 * q + 1] = t1 + z1 * (hl[2 * q + 1] - t1);
        }

        // ---- output projection: partial over own k, pair-sum, each half stores 8 ----
        u64t accO[8];
#pragma unroll
        for (int q = 0; q < 8; q++) {
            float l, h; up2(l, h, Lbp[q]);
            accO[q] = pk2(0.5f * l, 0.5f * h);
        }
#pragma unroll
        for (int i = 0; i < 32; i++) {
            u64t a = dup2(fmaxf(hl[i], 0.f));
            const u64t* wl = (const u64t*)(sLino + i * 16);
#pragma unroll
            for (int q = 0; q < 8; q++) fma2(accO[q], a, wl[q]);
        }
#pragma unroll
        for (int q = 0; q < 8; q++) accO[q] = pair_sum(accO[q]);

        if (valid) {
            float* op = out + ((((size_t)b_g * TT + t) * N_NODES + n_g) * OUTD) + o * 8;
            u64t s0 = sel64(o, accO[4], accO[0]);
            u64t s1 = sel64(o, accO[5], accO[1]);
            u64t s2 = sel64(o, accO[6], accO[2]);
            u64t s3 = sel64(o, accO[7], accO[3]);
            float x0, x1, x2, x3;
            up2(x0, x1, s0); up2(x2, x3, s1);
            ((float4*)op)[0] = make_float4(x0, x1, x2, x3);
            up2(x0, x1, s2); up2(x2, x3, s3);
            ((float4*)op)[1] = make_float4(x0, x1, x2, x3);
        }
    }
}

// ---------------- launch ----------------
extern "C" void kernel_launch(void* const* d_in, const int* in_sizes, int n_in,
                              void* d_out, int out_size) {
    const float* x   = (const float*)d_in[0];
    const int*   ei  = (const int*)d_in[1];
    const float* ew  = (const float*)d_in[2];
    const float* Wz  = (const float*)d_in[3];
    const float* bz  = (const float*)d_in[4];
    const float* Wr  = (const float*)d_in[5];
    const float* br  = (const float*)d_in[6];
    const float* Wh  = (const float*)d_in[7];
    const float* bh  = (const float*)d_in[8];
    const float* Lz  = (const float*)d_in[9];
    const float* Lzb = (const float*)d_in[10];
    const float* Lr  = (const float*)d_in[11];
    const float* Lrb = (const float*)d_in[12];
    const float* Lh  = (const float*)d_in[13];
    const float* Lhb = (const float*)d_in[14];
    const float* lw  = (const float*)d_in[15];
    const float* lb  = (const float*)d_in[16];
    float* out = (float*)d_out;

    int E = in_sizes[2];
    if (E > N_EDGES_MAX) E = N_EDGES_MAX;

    const int smem_bytes = SMEM_FLOATS * (int)sizeof(float);
    cudaFuncSetAttribute(k_steps, cudaFuncAttributeMaxDynamicSharedMemorySize, smem_bytes);

    k_xT_zero<<<(N_NODES * NC + 255) / 256, 256>>>(x);
    k_edge<<<(E + 255) / 256, 256>>>(ei, ew, E);
    k_scan_dinv<<<1, 1024>>>();
    k_scatter<<<(E + 255) / 256, 256>>>(ei, ew, E);
    k_agg_fold<<<(N_NODES + 7) / 8 + 1, 256>>>(Wz, bz, Wr, br, Wh, bh,
                                               Lz, Lzb, Lr, Lrb, Lh, Lhb);
    k_steps<<<GRID_STEPS, NTHREADS, smem_bytes>>>(Lz, Lr, Lh, lw, lb, out);
}